// round 3
// baseline (speedup 1.0000x reference)
#include <cuda_runtime.h>
#include <cuda_bf16.h>
#include <math.h>

// Problem dims
#define H   1024
#define H3  3072
#define V   50257
#define L   50
#define ENC 2048

// Scratch layout (floats)
#define A_OFF      0          // 1024 : h@W_h + attn_w_b
#define GH_OFF     1024       // 3072 : h@gru_whh + gru_bhh
#define B_OFF      4096       // 50*1024 : enc@W_e
#define XIN_OFF    55296      // 3072 : [emb_row, attn_applied]
#define XPRE_OFF   58368      // 1024 : xin@comb_W + comb_b (pre-relu)
#define GI_OFF     59392      // 3072 : relu(xpre)@gru_wih + gru_bih
#define HNEW_OFF   62464      // 1024
#define MAXBITS_OFF 63488     // 1 (as unsigned)
#define SUM_OFF    63489      // 1
#define SCRATCH_ELEMS 65536

__device__ float g_scratch[SCRATCH_ELEMS];

// order-preserving float->uint map for atomicMax
__device__ __forceinline__ unsigned f2o(float f) {
    unsigned u = __float_as_uint(f);
    return (u & 0x80000000u) ? ~u : (u | 0x80000000u);
}
__device__ __forceinline__ float o2f(unsigned u) {
    return (u & 0x80000000u) ? __uint_as_float(u ^ 0x80000000u) : __uint_as_float(~u);
}

// ---------------------------------------------------------------------------
// K0: reset scratch each launch (graph-replay safe): zero B, load biases.
// ---------------------------------------------------------------------------
__global__ void init_kernel(float* __restrict__ s,
                            const float* __restrict__ attn_w_b,
                            const float* __restrict__ gru_bhh,
                            const float* __restrict__ gru_bih,
                            const float* __restrict__ comb_b) {
    int gid = blockIdx.x * blockDim.x + threadIdx.x;
    int stride = gridDim.x * blockDim.x;
    for (int i = gid; i < L * H; i += stride) s[B_OFF + i] = 0.f;
    for (int i = gid; i < H;    i += stride) s[A_OFF + i] = attn_w_b[i];
    for (int i = gid; i < H3;   i += stride) s[GH_OFF + i] = gru_bhh[i];
    for (int i = gid; i < H3;   i += stride) s[GI_OFF + i] = gru_bih[i];
    for (int i = gid; i < H;    i += stride) s[XPRE_OFF + i] = comb_b[i];
    if (gid == 0) {
        ((unsigned*)s)[MAXBITS_OFF] = 0u;   // < f2o of any float
        s[SUM_OFF] = 0.f;
    }
}

// ---------------------------------------------------------------------------
// Generic split-K GEMV: out[j] += sum_k x[k] * W[k*N + j]
// grid.x covers N / blockDim, grid.y = K-splits (K % gridDim.y == 0).
// out must be pre-initialized with bias (init_kernel).
// ---------------------------------------------------------------------------
template <int RELU>
__global__ void gemv_splitk(const float* __restrict__ x,
                            const float* __restrict__ W,
                            float* __restrict__ out, int N, int K) {
    int j = blockIdx.x * blockDim.x + threadIdx.x;
    if (j >= N) return;
    int kchunk = K / gridDim.y;
    int k0 = blockIdx.y * kchunk;
    const float* Wp = W + (size_t)k0 * N + j;
    float acc = 0.f;
#pragma unroll 8
    for (int k = 0; k < kchunk; ++k) {
        float xv = __ldg(&x[k0 + k]);
        if (RELU) xv = fmaxf(xv, 0.f);
        acc = fmaf(xv, *Wp, acc);
        Wp += N;
    }
    atomicAdd(&out[j], acc);
}

// ---------------------------------------------------------------------------
// K2: B[l][j] = sum_k enc[l][k] * W_e[k][j]   (W_e = attn_w_W rows 1024..3071)
// Register-blocked over all 50 l's so each W_e element is read exactly once.
// grid (8 j-blocks of 128, 16 k-splits of 128). atomicAdd into zeroed B.
// ---------------------------------------------------------------------------
__global__ void enc_gemm_kernel(const float* __restrict__ enc,
                                const float* __restrict__ We,
                                float* __restrict__ B) {
    __shared__ float es[L * 64];
    int t = threadIdx.x;                 // 128 threads
    int j = blockIdx.x * 128 + t;        // 0..1023
    int k0 = blockIdx.y * 128;
    float acc[L];
#pragma unroll
    for (int l = 0; l < L; ++l) acc[l] = 0.f;

    for (int kt = 0; kt < 128; kt += 64) {
        int kb = k0 + kt;
        __syncthreads();
        for (int i = t; i < L * 64; i += 128) {
            int l = i >> 6, kk = i & 63;
            es[i] = enc[l * ENC + kb + kk];
        }
        __syncthreads();
        for (int kk = 0; kk < 64; ++kk) {
            float w = We[(size_t)(kb + kk) * H + j];
#pragma unroll
            for (int l = 0; l < L; ++l)
                acc[l] = fmaf(w, es[l * 64 + kk], acc[l]);
        }
    }
#pragma unroll
    for (int l = 0; l < L; ++l) atomicAdd(&B[l * H + j], acc[l]);
}

// ---------------------------------------------------------------------------
// K3 (single block, 1024 thr): e[l] = relu(a+B[l]) @ v + vb ; softmax -> attw;
// attn_applied = attw @ enc ; xin = [emb[idx], attn_applied]; write attw out.
// ---------------------------------------------------------------------------
__global__ void attn_combine_kernel(float* __restrict__ s,
                                    const float* __restrict__ enc,
                                    const float* __restrict__ v,
                                    const float* __restrict__ vb,
                                    const float* __restrict__ emb,
                                    const int* __restrict__ idx,
                                    float* __restrict__ attw_out) {
    __shared__ float se[L];
    __shared__ float sw[L];
    int t = threadIdx.x, warp = t >> 5, lane = t & 31;
    const float* a = s + A_OFF;
    const float* B = s + B_OFF;

    for (int l = warp; l < L; l += 32) {
        const float* Bl = B + l * H;
        float p = 0.f;
        for (int jj = lane; jj < H; jj += 32)
            p = fmaf(fmaxf(a[jj] + Bl[jj], 0.f), v[jj], p);
#pragma unroll
        for (int o = 16; o; o >>= 1) p += __shfl_xor_sync(0xffffffffu, p, o);
        if (lane == 0) se[l] = p + vb[0];
    }
    __syncthreads();

    if (warp == 0) {
        float e0 = (lane < L) ? se[lane] : -3.0e38f;
        float e1 = (lane + 32 < L) ? se[lane + 32] : -3.0e38f;
        float m = fmaxf(e0, e1);
#pragma unroll
        for (int o = 16; o; o >>= 1) m = fmaxf(m, __shfl_xor_sync(0xffffffffu, m, o));
        float x0 = (lane < L) ? expf(e0 - m) : 0.f;
        float x1 = (lane + 32 < L) ? expf(e1 - m) : 0.f;
        float ssum = x0 + x1;
#pragma unroll
        for (int o = 16; o; o >>= 1) ssum += __shfl_xor_sync(0xffffffffu, ssum, o);
        if (lane < L) sw[lane] = x0 / ssum;
        if (lane + 32 < L) sw[lane + 32] = x1 / ssum;
    }
    __syncthreads();

    if (t < L) attw_out[t] = sw[t];

    float* xin = s + XIN_OFF;
    int id = idx[0];
    xin[t] = emb[(size_t)id * H + t];
    for (int m = t; m < ENC; m += 1024) {
        float acc = 0.f;
#pragma unroll 10
        for (int l = 0; l < L; ++l) acc = fmaf(sw[l], enc[l * ENC + m], acc);
        xin[H + m] = acc;
    }
}

// ---------------------------------------------------------------------------
// K7: GRU gates (PyTorch order r,z,n) -> h_new (scratch + d_out region)
// ---------------------------------------------------------------------------
__global__ void gru_gate_kernel(float* __restrict__ s,
                                const float* __restrict__ h,
                                float* __restrict__ hnew_out) {
    int t = threadIdx.x;  // 1024
    const float* gi = s + GI_OFF;
    const float* gh = s + GH_OFF;
    float r = 1.f / (1.f + expf(-(gi[t] + gh[t])));
    float z = 1.f / (1.f + expf(-(gi[H + t] + gh[H + t])));
    float n = tanhf(gi[2 * H + t] + r * gh[2 * H + t]);
    float hn = (1.f - z) * n + z * h[t];
    s[HNEW_OFF + t] = hn;
    hnew_out[t] = hn;
}

// ---------------------------------------------------------------------------
// K8: logits[j] = hnew @ out_W[:,j] + out_b[j]; per-block max -> atomicMax
// ---------------------------------------------------------------------------
__global__ void logits_kernel(const float* __restrict__ hnew,
                              const float* __restrict__ W,
                              const float* __restrict__ bias,
                              float* __restrict__ logits,
                              unsigned* __restrict__ maxbits) {
    __shared__ float hs[H];
    __shared__ float wm[8];
    int t = threadIdx.x;  // 256
    for (int i = t; i < H; i += 256) hs[i] = hnew[i];
    __syncthreads();
    int j = blockIdx.x * 256 + t;
    float acc = -3.0e38f;
    if (j < V) {
        acc = bias[j];
        const float* Wp = W + j;
#pragma unroll 16
        for (int k = 0; k < H; ++k)
            acc = fmaf(hs[k], Wp[(size_t)k * V], acc);
        logits[j] = acc;
    }
    float m = acc;
#pragma unroll
    for (int o = 16; o; o >>= 1) m = fmaxf(m, __shfl_xor_sync(0xffffffffu, m, o));
    if ((t & 31) == 0) wm[t >> 5] = m;
    __syncthreads();
    if (t == 0) {
#pragma unroll
        for (int w = 1; w < 8; ++w) m = fmaxf(m, wm[w]);
        atomicMax(maxbits, f2o(m));
    }
}

// ---------------------------------------------------------------------------
// K9: sum exp(logit - max) -> atomicAdd
// ---------------------------------------------------------------------------
__global__ void sumexp_kernel(const float* __restrict__ logits,
                              const unsigned* __restrict__ maxbits,
                              float* __restrict__ gsum) {
    __shared__ float ws[8];
    float m = o2f(*maxbits);
    float acc = 0.f;
    int stride = gridDim.x * blockDim.x;
    for (int j = blockIdx.x * blockDim.x + threadIdx.x; j < V; j += stride)
        acc += expf(logits[j] - m);
#pragma unroll
    for (int o = 16; o; o >>= 1) acc += __shfl_xor_sync(0xffffffffu, acc, o);
    int t = threadIdx.x;
    if ((t & 31) == 0) ws[t >> 5] = acc;
    __syncthreads();
    if (t == 0) {
        float s = ws[0];
#pragma unroll
        for (int w = 1; w < 8; ++w) s += ws[w];
        atomicAdd(gsum, s);
    }
}

// ---------------------------------------------------------------------------
// K10: logprob = logit - max - log(sum)   (in place)
// ---------------------------------------------------------------------------
__global__ void finalize_kernel(float* __restrict__ logits,
                                const unsigned* __restrict__ maxbits,
                                const float* __restrict__ gsum) {
    int j = blockIdx.x * blockDim.x + threadIdx.x;
    if (j < V) {
        float lse = o2f(*maxbits) + logf(*gsum);
        logits[j] -= lse;
    }
}

// ---------------------------------------------------------------------------
extern "C" void kernel_launch(void* const* d_in, const int* in_sizes, int n_in,
                              void* d_out, int out_size) {
    const int*   idx      = (const int*)d_in[0];   // int64 LE: low word = value
    const float* hidden   = (const float*)d_in[1];
    const float* enc      = (const float*)d_in[2];
    const float* emb      = (const float*)d_in[3];
    const float* attn_w_W = (const float*)d_in[4];
    const float* attn_w_b = (const float*)d_in[5];
    const float* attn_v_W = (const float*)d_in[6];
    const float* attn_v_b = (const float*)d_in[7];
    const float* comb_W   = (const float*)d_in[8];
    const float* comb_b   = (const float*)d_in[9];
    const float* gru_wih  = (const float*)d_in[10];
    const float* gru_bih  = (const float*)d_in[11];
    const float* gru_whh  = (const float*)d_in[12];
    const float* gru_bhh  = (const float*)d_in[13];
    const float* out_W    = (const float*)d_in[14];
    const float* out_b    = (const float*)d_in[15];
    float* out = (float*)d_out;   // [V logprobs][H h_new][L attn_weights]

    float* s = nullptr;
    cudaGetSymbolAddress((void**)&s, g_scratch);
    unsigned* maxbits = (unsigned*)(s + MAXBITS_OFF);

    init_kernel<<<64, 256>>>(s, attn_w_b, gru_bhh, gru_bih, comb_b);

    // independent of attention path: a = h@W_h + b ; gh = h@gru_whh + bhh
    gemv_splitk<0><<<dim3(4, 8), 256>>>(hidden, attn_w_W, s + A_OFF, H, H);
    gemv_splitk<0><<<dim3(12, 8), 256>>>(hidden, gru_whh, s + GH_OFF, H3, H);

    // B = enc @ W_e
    enc_gemm_kernel<<<dim3(8, 16), 128>>>(enc, attn_w_W + (size_t)H * H, s + B_OFF);

    // scores -> softmax -> attn_applied -> xin ; writes attn_weights to out
    attn_combine_kernel<<<1, 1024>>>(s, enc, attn_v_W, attn_v_b, emb, idx,
                                     out + V + H);

    // xpre = xin @ comb_W + comb_b
    gemv_splitk<0><<<dim3(4, 12), 256>>>(s + XIN_OFF, comb_W, s + XPRE_OFF, H, H3);

    // gi = relu(xpre) @ gru_wih + bih
    gemv_splitk<1><<<dim3(12, 8), 256>>>(s + XPRE_OFF, gru_wih, s + GI_OFF, H3, H);

    // gates -> h_new (also to out)
    gru_gate_kernel<<<1, 1024>>>(s, hidden, out + V);

    // vocab GEMV + log-softmax
    logits_kernel<<<(V + 255) / 256, 256>>>(s + HNEW_OFF, out_W, out_b, out, maxbits);
    sumexp_kernel<<<64, 256>>>(out, maxbits, s + SUM_OFF);
    finalize_kernel<<<(V + 255) / 256, 256>>>(out, maxbits, s + SUM_OFF);
}

// round 4
// speedup vs baseline: 1.4963x; 1.4963x over previous
#include <cuda_runtime.h>
#include <cuda_bf16.h>
#include <math.h>

// Problem dims
#define H   1024
#define H3  3072
#define V   50257
#define L   50
#define ENC 2048

// Scratch layout (floats)
#define A_OFF      0          // 1024 : h@W_h + attn_w_b
#define GH_OFF     1024       // 3072 : h@gru_whh + gru_bhh
#define B_OFF      4096       // 50*1024 : enc@W_e
#define XIN_OFF    55296      // 3072 : [emb_row, attn_applied]
#define XPRE_OFF   58368      // 1024 : xin@comb_W + comb_b (pre-relu)
#define GI_OFF     59392      // 3072 : relu(xpre)@gru_wih + gru_bih
#define HNEW_OFF   62464      // 1024
#define MAXBITS_OFF 63488     // 1 (as unsigned)
#define SUM_OFF    63489      // 1
#define SCRATCH_ELEMS 65536

__device__ float g_scratch[SCRATCH_ELEMS];

// order-preserving float->uint map for atomicMax
__device__ __forceinline__ unsigned f2o(float f) {
    unsigned u = __float_as_uint(f);
    return (u & 0x80000000u) ? ~u : (u | 0x80000000u);
}
__device__ __forceinline__ float o2f(unsigned u) {
    return (u & 0x80000000u) ? __uint_as_float(u ^ 0x80000000u) : __uint_as_float(~u);
}

// ---------------------------------------------------------------------------
// K0: reset scratch each replay: zero B, preload biases into accumulators.
// ---------------------------------------------------------------------------
__global__ void init_kernel(float* __restrict__ s,
                            const float* __restrict__ attn_w_b,
                            const float* __restrict__ gru_bhh,
                            const float* __restrict__ gru_bih,
                            const float* __restrict__ comb_b) {
    int gid = blockIdx.x * blockDim.x + threadIdx.x;
    int stride = gridDim.x * blockDim.x;
    for (int i = gid; i < L * H; i += stride) s[B_OFF + i] = 0.f;
    for (int i = gid; i < H;    i += stride) s[A_OFF + i] = attn_w_b[i];
    for (int i = gid; i < H3;   i += stride) s[GH_OFF + i] = gru_bhh[i];
    for (int i = gid; i < H3;   i += stride) s[GI_OFF + i] = gru_bih[i];
    for (int i = gid; i < H;    i += stride) s[XPRE_OFF + i] = comb_b[i];
    if (gid == 0) {
        ((unsigned*)s)[MAXBITS_OFF] = 0u;   // < f2o of any float
        s[SUM_OFF] = 0.f;
    }
}

// ---------------------------------------------------------------------------
// Split-K GEMV, 2 cols/thread (float2): out[j] += sum_k x[k] * W[k*N + j]
// N even. out pre-initialized with bias.
// ---------------------------------------------------------------------------
template <int RELU>
__global__ void gemv2_splitk(const float* __restrict__ x,
                             const float* __restrict__ W,
                             float* __restrict__ out, int N, int K) {
    int j = (blockIdx.x * blockDim.x + threadIdx.x) * 2;
    if (j >= N) return;
    int kchunk = K / gridDim.y;
    int k0 = blockIdx.y * kchunk;
    const float* Wp = W + (size_t)k0 * N + j;
    float a0 = 0.f, a1 = 0.f;
#pragma unroll 8
    for (int k = 0; k < kchunk; ++k) {
        float xv = __ldg(&x[k0 + k]);
        if (RELU) xv = fmaxf(xv, 0.f);
        float2 w = *(const float2*)Wp;
        a0 = fmaf(xv, w.x, a0);
        a1 = fmaf(xv, w.y, a1);
        Wp += N;
    }
    atomicAdd(&out[j], a0);
    atomicAdd(&out[j + 1], a1);
}

// ---------------------------------------------------------------------------
// K2: B[l][j] = sum_k enc[l][k] * W_e[k][j]
// L-blocked by 10 per thread (grid.z = 5 groups), 16 K-splits, 256 thr.
// W_e re-read 5x but L2-resident (8 MB). acc[10] -> no spill, high occupancy.
// ---------------------------------------------------------------------------
#define LB 10
__global__ void enc_gemm_kernel(const float* __restrict__ enc,
                                const float* __restrict__ We,
                                float* __restrict__ B) {
    __shared__ float es[LB * 128];
    int t = threadIdx.x;                 // 256
    int j = blockIdx.x * 256 + t;        // 0..1023
    int k0 = blockIdx.y * 128;
    int l0 = blockIdx.z * LB;

    for (int i = t; i < LB * 128; i += 256) {
        int l = i >> 7, kk = i & 127;
        es[i] = enc[(l0 + l) * ENC + k0 + kk];
    }
    __syncthreads();

    float acc[LB];
#pragma unroll
    for (int l = 0; l < LB; ++l) acc[l] = 0.f;

    const float* Wp = We + (size_t)k0 * H + j;
#pragma unroll 8
    for (int kk = 0; kk < 128; ++kk) {
        float w = Wp[(size_t)kk * H];
#pragma unroll
        for (int l = 0; l < LB; ++l)
            acc[l] = fmaf(w, es[l * 128 + kk], acc[l]);
    }
#pragma unroll
    for (int l = 0; l < LB; ++l) atomicAdd(&B[(l0 + l) * H + j], acc[l]);
}

// ---------------------------------------------------------------------------
// K3 (single block, 1024 thr): e[l] = relu(a+B[l]) @ v + vb ; softmax -> attw;
// attn_applied = attw @ enc (float4) ; xin = [emb[idx], attn_applied].
// ---------------------------------------------------------------------------
__global__ void attn_combine_kernel(float* __restrict__ s,
                                    const float* __restrict__ enc,
                                    const float* __restrict__ v,
                                    const float* __restrict__ vb,
                                    const float* __restrict__ emb,
                                    const int* __restrict__ idx,
                                    float* __restrict__ attw_out) {
    __shared__ float se[L];
    __shared__ float sw[L];
    int t = threadIdx.x, warp = t >> 5, lane = t & 31;
    const float* a = s + A_OFF;
    const float* B = s + B_OFF;

    for (int l = warp; l < L; l += 32) {
        const float* Bl = B + l * H;
        float p = 0.f;
        for (int jj = lane; jj < H; jj += 32)
            p = fmaf(fmaxf(a[jj] + Bl[jj], 0.f), v[jj], p);
#pragma unroll
        for (int o = 16; o; o >>= 1) p += __shfl_xor_sync(0xffffffffu, p, o);
        if (lane == 0) se[l] = p + vb[0];
    }
    __syncthreads();

    if (warp == 0) {
        float e0 = (lane < L) ? se[lane] : -3.0e38f;
        float e1 = (lane + 32 < L) ? se[lane + 32] : -3.0e38f;
        float m = fmaxf(e0, e1);
#pragma unroll
        for (int o = 16; o; o >>= 1) m = fmaxf(m, __shfl_xor_sync(0xffffffffu, m, o));
        float x0 = (lane < L) ? expf(e0 - m) : 0.f;
        float x1 = (lane + 32 < L) ? expf(e1 - m) : 0.f;
        float ssum = x0 + x1;
#pragma unroll
        for (int o = 16; o; o >>= 1) ssum += __shfl_xor_sync(0xffffffffu, ssum, o);
        if (lane < L) sw[lane] = x0 / ssum;
        if (lane + 32 < L) sw[lane + 32] = x1 / ssum;
    }
    __syncthreads();

    if (t < L) attw_out[t] = sw[t];

    float* xin = s + XIN_OFF;
    int id = idx[0];
    xin[t] = emb[(size_t)id * H + t];

    // attn_applied: 512 threads each produce one float4 of the 2048-wide row
    if (t < ENC / 4) {
        float4 acc = make_float4(0.f, 0.f, 0.f, 0.f);
#pragma unroll 10
        for (int l = 0; l < L; ++l) {
            float wl = sw[l];
            float4 e4 = *(const float4*)(enc + l * ENC + t * 4);
            acc.x = fmaf(wl, e4.x, acc.x);
            acc.y = fmaf(wl, e4.y, acc.y);
            acc.z = fmaf(wl, e4.z, acc.z);
            acc.w = fmaf(wl, e4.w, acc.w);
        }
        *(float4*)(xin + H + t * 4) = acc;
    }
}

// ---------------------------------------------------------------------------
// K7: GRU gates (PyTorch order r,z,n) -> h_new
// ---------------------------------------------------------------------------
__global__ void gru_gate_kernel(float* __restrict__ s,
                                const float* __restrict__ h,
                                float* __restrict__ hnew_out) {
    int t = threadIdx.x;  // 1024
    const float* gi = s + GI_OFF;
    const float* gh = s + GH_OFF;
    float r = 1.f / (1.f + expf(-(gi[t] + gh[t])));
    float z = 1.f / (1.f + expf(-(gi[H + t] + gh[H + t])));
    float n = tanhf(gi[2 * H + t] + r * gh[2 * H + t]);
    float hn = (1.f - z) * n + z * h[t];
    s[HNEW_OFF + t] = hn;
    hnew_out[t] = hn;
}

// ---------------------------------------------------------------------------
// K8: logits[j] = hnew @ out_W[:,j] + out_b[j]; per-block max -> atomicMax
// 128-thread blocks, 393 blocks all co-resident (~2.7/SM) for BW saturation.
// ---------------------------------------------------------------------------
__global__ void logits_kernel(const float* __restrict__ hnew,
                              const float* __restrict__ W,
                              const float* __restrict__ bias,
                              float* __restrict__ logits,
                              unsigned* __restrict__ maxbits) {
    __shared__ float hs[H];
    __shared__ float wm[4];
    int t = threadIdx.x;  // 128
    for (int i = t; i < H; i += 128) hs[i] = hnew[i];
    __syncthreads();
    int j = blockIdx.x * 128 + t;
    float acc = -3.0e38f;
    if (j < V) {
        acc = bias[j];
        const float* Wp = W + j;
#pragma unroll 16
        for (int k = 0; k < H; ++k)
            acc = fmaf(hs[k], Wp[(size_t)k * V], acc);
        logits[j] = acc;
    }
    float m = acc;
#pragma unroll
    for (int o = 16; o; o >>= 1) m = fmaxf(m, __shfl_xor_sync(0xffffffffu, m, o));
    if ((t & 31) == 0) wm[t >> 5] = m;
    __syncthreads();
    if (t == 0) {
#pragma unroll
        for (int w = 1; w < 4; ++w) m = fmaxf(m, wm[w]);
        atomicMax(maxbits, f2o(m));
    }
}

// ---------------------------------------------------------------------------
// K9: sum exp(logit - max) -> atomicAdd
// ---------------------------------------------------------------------------
__global__ void sumexp_kernel(const float* __restrict__ logits,
                              const unsigned* __restrict__ maxbits,
                              float* __restrict__ gsum) {
    __shared__ float ws[8];
    float m = o2f(*maxbits);
    float acc = 0.f;
    int stride = gridDim.x * blockDim.x;
    for (int j = blockIdx.x * blockDim.x + threadIdx.x; j < V; j += stride)
        acc += expf(logits[j] - m);
#pragma unroll
    for (int o = 16; o; o >>= 1) acc += __shfl_xor_sync(0xffffffffu, acc, o);
    int t = threadIdx.x;
    if ((t & 31) == 0) ws[t >> 5] = acc;
    __syncthreads();
    if (t == 0) {
        float s = ws[0];
#pragma unroll
        for (int w = 1; w < 8; ++w) s += ws[w];
        atomicAdd(gsum, s);
    }
}

// ---------------------------------------------------------------------------
// K10: logprob = logit - max - log(sum)   (in place)
// ---------------------------------------------------------------------------
__global__ void finalize_kernel(float* __restrict__ logits,
                                const unsigned* __restrict__ maxbits,
                                const float* __restrict__ gsum) {
    int j = blockIdx.x * blockDim.x + threadIdx.x;
    if (j < V) {
        float lse = o2f(*maxbits) + logf(*gsum);
        logits[j] -= lse;
    }
}

// ---------------------------------------------------------------------------
extern "C" void kernel_launch(void* const* d_in, const int* in_sizes, int n_in,
                              void* d_out, int out_size) {
    const int*   idx      = (const int*)d_in[0];   // int64 LE: low word = value
    const float* hidden   = (const float*)d_in[1];
    const float* enc      = (const float*)d_in[2];
    const float* emb      = (const float*)d_in[3];
    const float* attn_w_W = (const float*)d_in[4];
    const float* attn_w_b = (const float*)d_in[5];
    const float* attn_v_W = (const float*)d_in[6];
    const float* attn_v_b = (const float*)d_in[7];
    const float* comb_W   = (const float*)d_in[8];
    const float* comb_b   = (const float*)d_in[9];
    const float* gru_wih  = (const float*)d_in[10];
    const float* gru_bih  = (const float*)d_in[11];
    const float* gru_whh  = (const float*)d_in[12];
    const float* gru_bhh  = (const float*)d_in[13];
    const float* out_W    = (const float*)d_in[14];
    const float* out_b    = (const float*)d_in[15];
    float* out = (float*)d_out;   // [V logprobs][H h_new][L attn_weights]

    float* s = nullptr;
    cudaGetSymbolAddress((void**)&s, g_scratch);
    unsigned* maxbits = (unsigned*)(s + MAXBITS_OFF);

    init_kernel<<<64, 256>>>(s, attn_w_b, gru_bhh, gru_bih, comb_b);

    // independent of attention path: a = h@W_h + b ; gh = h@gru_whh + bhh
    gemv2_splitk<0><<<dim3(2, 16), 256>>>(hidden, attn_w_W, s + A_OFF, H, H);
    gemv2_splitk<0><<<dim3(6, 16), 256>>>(hidden, gru_whh, s + GH_OFF, H3, H);

    // B = enc @ W_e   (grid: 4 j-tiles, 16 k-splits, 5 l-groups)
    enc_gemm_kernel<<<dim3(4, 16, 5), 256>>>(enc, attn_w_W + (size_t)H * H,
                                             s + B_OFF);

    // scores -> softmax -> attn_applied -> xin ; writes attn_weights to out
    attn_combine_kernel<<<1, 1024>>>(s, enc, attn_v_W, attn_v_b, emb, idx,
                                     out + V + H);

    // xpre = xin @ comb_W + comb_b
    gemv2_splitk<0><<<dim3(2, 24), 256>>>(s + XIN_OFF, comb_W, s + XPRE_OFF, H, H3);

    // gi = relu(xpre) @ gru_wih + bih
    gemv2_splitk<1><<<dim3(6, 16), 256>>>(s + XPRE_OFF, gru_wih, s + GI_OFF, H3, H);

    // gates -> h_new (also to out)
    gru_gate_kernel<<<1, 1024>>>(s, hidden, out + V);

    // vocab GEMV + log-softmax
    logits_kernel<<<(V + 127) / 128, 128>>>(s + HNEW_OFF, out_W, out_b, out, maxbits);
    sumexp_kernel<<<148, 256>>>(out, maxbits, s + SUM_OFF);
    finalize_kernel<<<(V + 255) / 256, 256>>>(out, maxbits, s + SUM_OFF);
}

// round 5
// speedup vs baseline: 1.7597x; 1.1760x over previous
#include <cuda_runtime.h>
#include <cuda_bf16.h>
#include <math.h>

// Problem dims
#define H   1024
#define H3  3072
#define V   50257
#define L   50
#define ENC 2048

// Scratch layout (floats)
#define A_OFF      0          // 1024 : h@W_h + attn_w_b
#define GH_OFF     1024       // 3072 : h@gru_whh + gru_bhh
#define B_OFF      4096       // 50*1024 : enc@W_e
#define XIN_OFF    55296      // 3072 : [emb_row, attn_applied]
#define XPRE_OFF   58368      // 1024 : xin@comb_W + comb_b (pre-relu)
#define GI_OFF     59392      // 3072 : relu(xpre)@gru_wih + gru_bih
#define HNEW_OFF   62464      // 1024
#define SE_OFF     63600      // 50 : attention scores
#define SUM_OFF    63520      // 1  : global sum(exp(logit))
#define SCRATCH_ELEMS 65536

__device__ float g_scratch[SCRATCH_ELEMS];

// ---------------------------------------------------------------------------
// K0: reset scratch each replay: zero B, preload biases into accumulators.
// ---------------------------------------------------------------------------
__global__ void init_kernel(float* __restrict__ s,
                            const float* __restrict__ attn_w_b,
                            const float* __restrict__ gru_bhh,
                            const float* __restrict__ gru_bih,
                            const float* __restrict__ comb_b) {
    int gid = blockIdx.x * blockDim.x + threadIdx.x;
    int stride = gridDim.x * blockDim.x;
    for (int i = gid; i < L * H; i += stride) s[B_OFF + i] = 0.f;
    for (int i = gid; i < H;    i += stride) s[A_OFF + i] = attn_w_b[i];
    for (int i = gid; i < H3;   i += stride) s[GH_OFF + i] = gru_bhh[i];
    for (int i = gid; i < H3;   i += stride) s[GI_OFF + i] = gru_bih[i];
    for (int i = gid; i < H;    i += stride) s[XPRE_OFF + i] = comb_b[i];
    if (gid == 0) s[SUM_OFF] = 0.f;
}

// ---------------------------------------------------------------------------
// K1: fused dual GEMV on h (K=1024): block.x==0 -> a = h@W_h (N=1024)
//     blocks 1..3 -> gh = h@gru_whh (N=3072). 4 cols/thread, 32 K-splits.
// ---------------------------------------------------------------------------
__global__ void dual_gemv_h(const float* __restrict__ h,
                            const float* __restrict__ Wa,
                            const float* __restrict__ Wg,
                            float* __restrict__ s) {
    int bx = blockIdx.x;
    const float* W;
    float* out;
    int N, jb;
    if (bx == 0) { W = Wa; out = s + A_OFF;  N = 1024; jb = 0; }
    else         { W = Wg; out = s + GH_OFF; N = 3072; jb = (bx - 1) * 1024; }
    int j = jb + threadIdx.x * 4;
    int k0 = blockIdx.y * 32;              // gridDim.y == 32
    const float* Wp = W + (size_t)k0 * N + j;
    float a0 = 0.f, a1 = 0.f, a2 = 0.f, a3 = 0.f;
#pragma unroll 8
    for (int k = 0; k < 32; ++k) {
        float xv = __ldg(&h[k0 + k]);
        float4 w = *(const float4*)Wp;
        a0 = fmaf(xv, w.x, a0);
        a1 = fmaf(xv, w.y, a1);
        a2 = fmaf(xv, w.z, a2);
        a3 = fmaf(xv, w.w, a3);
        Wp += N;
    }
    atomicAdd(&out[j],     a0);
    atomicAdd(&out[j + 1], a1);
    atomicAdd(&out[j + 2], a2);
    atomicAdd(&out[j + 3], a3);
}

// ---------------------------------------------------------------------------
// Generic split-K GEMV, 4 cols/thread (float4). out pre-initialized w/ bias.
// ---------------------------------------------------------------------------
template <int RELU>
__global__ void gemv4_splitk(const float* __restrict__ x,
                             const float* __restrict__ W,
                             float* __restrict__ out, int N, int K) {
    int j = (blockIdx.x * blockDim.x + threadIdx.x) * 4;
    if (j >= N) return;
    int kchunk = K / gridDim.y;
    int k0 = blockIdx.y * kchunk;
    const float* Wp = W + (size_t)k0 * N + j;
    float a0 = 0.f, a1 = 0.f, a2 = 0.f, a3 = 0.f;
#pragma unroll 8
    for (int k = 0; k < kchunk; ++k) {
        float xv = __ldg(&x[k0 + k]);
        if (RELU) xv = fmaxf(xv, 0.f);
        float4 w = *(const float4*)Wp;
        a0 = fmaf(xv, w.x, a0);
        a1 = fmaf(xv, w.y, a1);
        a2 = fmaf(xv, w.z, a2);
        a3 = fmaf(xv, w.w, a3);
        Wp += N;
    }
    atomicAdd(&out[j],     a0);
    atomicAdd(&out[j + 1], a1);
    atomicAdd(&out[j + 2], a2);
    atomicAdd(&out[j + 3], a3);
}

// ---------------------------------------------------------------------------
// K2: B[l][j] += sum_k enc[l][k] * W_e[k][j]
// grid (4 j-tiles, 32 k-splits of 64, 5 l-groups of LB=10). 640 blocks.
// ---------------------------------------------------------------------------
#define LB 10
__global__ void enc_gemm_kernel(const float* __restrict__ enc,
                                const float* __restrict__ We,
                                float* __restrict__ B) {
    __shared__ float es[LB * 64];
    int t = threadIdx.x;                 // 256
    int j = blockIdx.x * 256 + t;        // 0..1023
    int k0 = blockIdx.y * 64;
    int l0 = blockIdx.z * LB;

    for (int i = t; i < LB * 64; i += 256) {
        int l = i >> 6, kk = i & 63;
        es[i] = enc[(l0 + l) * ENC + k0 + kk];
    }
    __syncthreads();

    float acc[LB];
#pragma unroll
    for (int l = 0; l < LB; ++l) acc[l] = 0.f;

    const float* Wp = We + (size_t)k0 * H + j;
#pragma unroll 8
    for (int kk = 0; kk < 64; ++kk) {
        float w = Wp[(size_t)kk * H];
#pragma unroll
        for (int l = 0; l < LB; ++l)
            acc[l] = fmaf(w, es[l * 64 + kk], acc[l]);
    }
#pragma unroll
    for (int l = 0; l < LB; ++l) atomicAdd(&B[(l0 + l) * H + j], acc[l]);
}

// ---------------------------------------------------------------------------
// K3: scores: se[l] = relu(a + B[l]) @ v + vb      (50 blocks x 256)
// ---------------------------------------------------------------------------
__global__ void scores_kernel(float* __restrict__ s,
                              const float* __restrict__ v,
                              const float* __restrict__ vb) {
    __shared__ float ws[8];
    int l = blockIdx.x, t = threadIdx.x, lane = t & 31, warp = t >> 5;
    const float* a = s + A_OFF;
    const float* Bl = s + B_OFF + l * H;
    float p = 0.f;
    for (int jj = t; jj < H; jj += 256)
        p = fmaf(fmaxf(a[jj] + Bl[jj], 0.f), v[jj], p);
#pragma unroll
    for (int o = 16; o; o >>= 1) p += __shfl_xor_sync(0xffffffffu, p, o);
    if (lane == 0) ws[warp] = p;
    __syncthreads();
    if (t == 0) {
        float acc = ws[0];
#pragma unroll
        for (int w = 1; w < 8; ++w) acc += ws[w];
        s[SE_OFF + l] = acc + vb[0];
    }
}

// ---------------------------------------------------------------------------
// K4: softmax(se) -> attn weights; attn_applied = w @ enc; xin assembly.
// grid 17 x 128: blocks 0..15 each compute 128 cols of attn_applied,
// block 16 writes attw_out and copies the embedding row.
// ---------------------------------------------------------------------------
__global__ void attn_apply_kernel(float* __restrict__ s,
                                  const float* __restrict__ enc,
                                  const float* __restrict__ emb,
                                  const int* __restrict__ idx,
                                  float* __restrict__ attw_out) {
    __shared__ float se[L];
    __shared__ float sw[L];
    int t = threadIdx.x;
    if (t < L) se[t] = s[SE_OFF + t];
    __syncthreads();
    if (t < L) {
        float m = -3.0e38f;
#pragma unroll
        for (int l = 0; l < L; ++l) m = fmaxf(m, se[l]);
        float sum = 0.f;
#pragma unroll
        for (int l = 0; l < L; ++l) sum += expf(se[l] - m);
        sw[t] = expf(se[t] - m) / sum;
    }
    __syncthreads();

    float* xin = s + XIN_OFF;
    int b = blockIdx.x;
    if (b < 16) {
        int col = b * 128 + t;               // 0..2047
        float acc = 0.f;
#pragma unroll 10
        for (int l = 0; l < L; ++l)
            acc = fmaf(sw[l], enc[l * ENC + col], acc);
        xin[H + col] = acc;
    } else {
        if (t < L) attw_out[t] = sw[t];
        int id = idx[0];
        for (int i = t; i < H; i += 128)
            xin[i] = emb[(size_t)id * H + i];
    }
}

// ---------------------------------------------------------------------------
// K7: GRU gates (PyTorch order r,z,n) -> h_new
// ---------------------------------------------------------------------------
__global__ void gru_gate_kernel(float* __restrict__ s,
                                const float* __restrict__ h,
                                float* __restrict__ hnew_out) {
    int t = threadIdx.x;  // 1024
    const float* gi = s + GI_OFF;
    const float* gh = s + GH_OFF;
    float r = 1.f / (1.f + expf(-(gi[t] + gh[t])));
    float z = 1.f / (1.f + expf(-(gi[H + t] + gh[H + t])));
    float n = tanhf(gi[2 * H + t] + r * gh[2 * H + t]);
    float hn = (1.f - z) * n + z * h[t];
    s[HNEW_OFF + t] = hn;
    hnew_out[t] = hn;
}

// ---------------------------------------------------------------------------
// K8: logits[j] = hnew @ out_W[:,j] + out_b[j]; block-sum exp(logit) -> gsum.
// 64-thread blocks (786 blocks, ~5.3/SM) for load balance + BW.
// ---------------------------------------------------------------------------
__global__ void logits_kernel(const float* __restrict__ hnew,
                              const float* __restrict__ W,
                              const float* __restrict__ bias,
                              float* __restrict__ logits,
                              float* __restrict__ gsum) {
    __shared__ float hs[H];
    int t = threadIdx.x;  // 64
    for (int i = t; i < H; i += 64) hs[i] = hnew[i];
    __syncthreads();
    int j = blockIdx.x * 64 + t;
    float ex = 0.f;
    if (j < V) {
        float acc = bias[j];
        const float* Wp = W + j;
#pragma unroll 32
        for (int k = 0; k < H; ++k)
            acc = fmaf(hs[k], Wp[(size_t)k * V], acc);
        logits[j] = acc;
        ex = expf(acc);
    }
#pragma unroll
    for (int o = 16; o; o >>= 1) ex += __shfl_xor_sync(0xffffffffu, ex, o);
    if ((t & 31) == 0) atomicAdd(gsum, ex);
}

// ---------------------------------------------------------------------------
// K10: logprob = logit - log(sum)   (in place)
// ---------------------------------------------------------------------------
__global__ void finalize_kernel(float* __restrict__ logits,
                                const float* __restrict__ gsum) {
    int j = blockIdx.x * blockDim.x + threadIdx.x;
    if (j < V) logits[j] -= logf(*gsum);
}

// ---------------------------------------------------------------------------
extern "C" void kernel_launch(void* const* d_in, const int* in_sizes, int n_in,
                              void* d_out, int out_size) {
    const int*   idx      = (const int*)d_in[0];   // int64 LE: low word = value
    const float* hidden   = (const float*)d_in[1];
    const float* enc      = (const float*)d_in[2];
    const float* emb      = (const float*)d_in[3];
    const float* attn_w_W = (const float*)d_in[4];
    const float* attn_w_b = (const float*)d_in[5];
    const float* attn_v_W = (const float*)d_in[6];
    const float* attn_v_b = (const float*)d_in[7];
    const float* comb_W   = (const float*)d_in[8];
    const float* comb_b   = (const float*)d_in[9];
    const float* gru_wih  = (const float*)d_in[10];
    const float* gru_bih  = (const float*)d_in[11];
    const float* gru_whh  = (const float*)d_in[12];
    const float* gru_bhh  = (const float*)d_in[13];
    const float* out_W    = (const float*)d_in[14];
    const float* out_b    = (const float*)d_in[15];
    float* out = (float*)d_out;   // [V logprobs][H h_new][L attn_weights]

    float* s = nullptr;
    cudaGetSymbolAddress((void**)&s, g_scratch);

    init_kernel<<<64, 256>>>(s, attn_w_b, gru_bhh, gru_bih, comb_b);

    // a = h@W_h + b ; gh = h@gru_whh + bhh  (one fused launch)
    dual_gemv_h<<<dim3(4, 32), 256>>>(hidden, attn_w_W, gru_whh, s);

    // B = enc @ W_e
    enc_gemm_kernel<<<dim3(4, 32, 5), 256>>>(enc, attn_w_W + (size_t)H * H,
                                             s + B_OFF);

    // scores, softmax + apply + xin assembly (writes attn_weights to out)
    scores_kernel<<<L, 256>>>(s, attn_v_W, attn_v_b);
    attn_apply_kernel<<<17, 128>>>(s, enc, emb, idx, out + V + H);

    // xpre = xin @ comb_W + comb_b
    gemv4_splitk<0><<<dim3(1, 32), 256>>>(s + XIN_OFF, comb_W, s + XPRE_OFF,
                                          H, H3);

    // gi = relu(xpre) @ gru_wih + bih
    gemv4_splitk<1><<<dim3(3, 32), 256>>>(s + XPRE_OFF, gru_wih, s + GI_OFF,
                                          H3, H);

    // gates -> h_new (also to out)
    gru_gate_kernel<<<1, 1024>>>(s, hidden, out + V);

    // vocab GEMV + fused sum(exp) ; then log-softmax finalize
    logits_kernel<<<(V + 63) / 64, 64>>>(s + HNEW_OFF, out_W, out_b, out,
                                         s + SUM_OFF);
    finalize_kernel<<<(V + 255) / 256, 256>>>(out, s + SUM_OFF);
}

// round 8
// speedup vs baseline: 2.0130x; 1.1440x over previous
#include <cuda_runtime.h>
#include <cuda_bf16.h>
#include <math.h>

// Problem dims
#define H   1024
#define H3  3072
#define V   50257
#define L   50
#define ENC 2048

// Scratch layout (floats)
#define A_OFF      0          // 1024 : h@W_h + attn_w_b
#define GH_OFF     1024       // 3072 : h@gru_whh + gru_bhh
#define B_OFF      4096       // 50*1024 : enc@W_e
#define XIN_OFF    55296      // 3072 : [emb_row, attn_applied]
#define XPRE_OFF   58368      // 1024 : xin@comb_W + comb_b (pre-relu)
#define GI_OFF     59392      // 3072 : relu(xpre)@gru_wih + gru_bih
#define HNEW_OFF   62464      // 1024
#define SE_OFF     63600      // 50 : attention scores
#define SUM_OFF    63520      // 1  : global sum(exp(logit))
#define SCRATCH_ELEMS 65536

__device__ float g_scratch[SCRATCH_ELEMS];

// Self-resetting grid barriers (arrive/depart pairs). Zero-initialized at
// module load; the last departer resets both counters, so every kernel
// execution (and every graph replay) starts from 0. No external reset needed.
__device__ unsigned g_arrive[8];
__device__ unsigned g_depart[8];

__device__ __forceinline__ void grid_bar(int i, unsigned n) {
    __threadfence();
    __syncthreads();
    if (threadIdx.x == 0) {
        atomicAdd(&g_arrive[i], 1u);
        while (*(volatile unsigned*)&g_arrive[i] < n) __nanosleep(64);
        unsigned d = atomicAdd(&g_depart[i], 1u);
        if (d == n - 1u) {                 // all blocks passed the spin
            *(volatile unsigned*)&g_depart[i] = 0u;
            __threadfence();
            *(volatile unsigned*)&g_arrive[i] = 0u;
        }
    }
    __syncthreads();
    __threadfence();
}

// ---------------------------------------------------------------------------
// Fused small-op chain: one persistent kernel, 148 blocks x 256 threads.
// P0 init -> P1 {a,gh GEMVs + enc GEMM} -> P2 scores -> P3 softmax/apply/xin
// -> P4 comb GEMV -> P5 gih GEMV -> P6 GRU gates.
// ---------------------------------------------------------------------------
#define LB 10
__global__ void __launch_bounds__(256, 1)
fused_chain_kernel(const float* __restrict__ hidden,
                   const float* __restrict__ enc,
                   const float* __restrict__ emb,
                   const int*   __restrict__ idx,
                   const float* __restrict__ attn_w_W,
                   const float* __restrict__ attn_w_b,
                   const float* __restrict__ attn_v_W,
                   const float* __restrict__ attn_v_b,
                   const float* __restrict__ comb_W,
                   const float* __restrict__ comb_b,
                   const float* __restrict__ gru_wih,
                   const float* __restrict__ gru_bih,
                   const float* __restrict__ gru_whh,
                   const float* __restrict__ gru_bhh,
                   float* __restrict__ s,
                   float* __restrict__ hnew_out,
                   float* __restrict__ attw_out) {
    __shared__ float sm[704];      // enc tile (640) / softmax se+sw (100)
    __shared__ float ws[8];
    const unsigned NBLK = gridDim.x;     // 148
    const int bid = blockIdx.x;
    const int t = threadIdx.x;
    const int lane = t & 31, warp = t >> 5;

    // ---- P0: init accumulators with biases, zero B, reset gsum ----
    {
        int gid = bid * 256 + t, stride = NBLK * 256;
        for (int i = gid; i < L * H; i += stride) s[B_OFF + i] = 0.f;
        for (int i = gid; i < H;    i += stride) s[A_OFF + i] = attn_w_b[i];
        for (int i = gid; i < H3;   i += stride) s[GH_OFF + i] = gru_bhh[i];
        for (int i = gid; i < H3;   i += stride) s[GI_OFF + i] = gru_bih[i];
        for (int i = gid; i < H;    i += stride) s[XPRE_OFF + i] = comb_b[i];
        if (gid == 0) s[SUM_OFF] = 0.f;
    }
    grid_bar(0, NBLK);

    // ---- P1: units 0..127 dual h-GEMV; units 128..767 enc GEMM ----
    for (int u = bid; u < 768; u += NBLK) {
        if (u < 128) {
            int ju = u & 3, ku = u >> 2;           // 32 k-splits of 32
            const float* W; float* out; int N, jb;
            if (ju == 0) { W = attn_w_W; out = s + A_OFF;  N = 1024; jb = 0; }
            else         { W = gru_whh;  out = s + GH_OFF; N = 3072; jb = (ju - 1) * 1024; }
            int j = jb + t * 4;
            int k0 = ku * 32;
            const float* Wp = W + (size_t)k0 * N + j;
            float a0 = 0.f, a1 = 0.f, a2 = 0.f, a3 = 0.f;
#pragma unroll 8
            for (int k = 0; k < 32; ++k) {
                float xv = __ldg(&hidden[k0 + k]);
                float4 w = *(const float4*)Wp;
                a0 = fmaf(xv, w.x, a0); a1 = fmaf(xv, w.y, a1);
                a2 = fmaf(xv, w.z, a2); a3 = fmaf(xv, w.w, a3);
                Wp += N;
            }
            atomicAdd(&out[j],     a0); atomicAdd(&out[j + 1], a1);
            atomicAdd(&out[j + 2], a2); atomicAdd(&out[j + 3], a3);
        } else {
            int e = u - 128;                        // 640 units: 4j x 32k x 5l
            int uj = e & 3, uk = (e >> 2) & 31, ul = e >> 7;
            int j = uj * 256 + t, k0 = uk * 64, l0 = ul * LB;
            __syncthreads();
            for (int i = t; i < LB * 64; i += 256) {
                int l = i >> 6, kk = i & 63;
                sm[i] = enc[(l0 + l) * ENC + k0 + kk];
            }
            __syncthreads();
            float acc[LB];
#pragma unroll
            for (int l = 0; l < LB; ++l) acc[l] = 0.f;
            const float* Wp = attn_w_W + (size_t)H * H + (size_t)k0 * H + j;
#pragma unroll 8
            for (int kk = 0; kk < 64; ++kk) {
                float w = Wp[(size_t)kk * H];
#pragma unroll
                for (int l = 0; l < LB; ++l)
                    acc[l] = fmaf(w, sm[l * 64 + kk], acc[l]);
            }
#pragma unroll
            for (int l = 0; l < LB; ++l)
                atomicAdd(&s[B_OFF + (l0 + l) * H + j], acc[l]);
        }
    }
    grid_bar(1, NBLK);

    // ---- P2: scores se[l] = relu(a + B[l]) @ v + vb  (blocks 0..49) ----
    if (bid < L) {
        const float* a  = s + A_OFF;
        const float* Bl = s + B_OFF + bid * H;
        float p = 0.f;
        for (int jj = t; jj < H; jj += 256)
            p = fmaf(fmaxf(a[jj] + Bl[jj], 0.f), attn_v_W[jj], p);
#pragma unroll
        for (int o = 16; o; o >>= 1) p += __shfl_xor_sync(0xffffffffu, p, o);
        if (lane == 0) ws[warp] = p;
        __syncthreads();
        if (t == 0) {
            float acc = ws[0];
#pragma unroll
            for (int w = 1; w < 8; ++w) acc += ws[w];
            s[SE_OFF + bid] = acc + attn_v_b[0];
        }
    }
    grid_bar(2, NBLK);

    // ---- P3: softmax + attn_applied + xin assembly (blocks 0..8) ----
    if (bid <= 8) {
        float* se = sm;        // [50]
        float* sw = sm + 64;   // [50]
        if (t < L) se[t] = s[SE_OFF + t];
        __syncthreads();
        if (t < L) {
            float m = -3.0e38f;
#pragma unroll
            for (int l = 0; l < L; ++l) m = fmaxf(m, se[l]);
            float sum = 0.f;
#pragma unroll
            for (int l = 0; l < L; ++l) sum += expf(se[l] - m);
            sw[t] = expf(se[t] - m) / sum;
        }
        __syncthreads();
        float* xin = s + XIN_OFF;
        if (bid < 8) {
            int col = bid * 256 + t;               // 0..2047
            float acc = 0.f;
#pragma unroll 10
            for (int l = 0; l < L; ++l)
                acc = fmaf(sw[l], enc[l * ENC + col], acc);
            xin[H + col] = acc;
        } else {
            if (t < L) attw_out[t] = sw[t];
            int id = idx[0];
            for (int i = t; i < H; i += 256)
                xin[i] = emb[(size_t)id * H + i];
        }
    }
    grid_bar(3, NBLK);

    // ---- P4: xpre += xin @ comb_W   (64 k-splits of 48) ----
    if (bid < 64) {
        int j = t * 4;
        int k0 = bid * 48;
        const float* Wp = comb_W + (size_t)k0 * H + j;
        float a0 = 0.f, a1 = 0.f, a2 = 0.f, a3 = 0.f;
#pragma unroll 8
        for (int k = 0; k < 48; ++k) {
            float xv = s[XIN_OFF + k0 + k];
            float4 w = *(const float4*)Wp;
            a0 = fmaf(xv, w.x, a0); a1 = fmaf(xv, w.y, a1);
            a2 = fmaf(xv, w.z, a2); a3 = fmaf(xv, w.w, a3);
            Wp += H;
        }
        atomicAdd(&s[XPRE_OFF + j],     a0); atomicAdd(&s[XPRE_OFF + j + 1], a1);
        atomicAdd(&s[XPRE_OFF + j + 2], a2); atomicAdd(&s[XPRE_OFF + j + 3], a3);
    }
    grid_bar(4, NBLK);

    // ---- P5: gi += relu(xpre) @ gru_wih  (3 j-tiles x 32 k-splits) ----
    if (bid < 96) {
        int ju = bid % 3, ku = bid / 3;
        int j = ju * 1024 + t * 4;
        int k0 = ku * 32;
        const float* Wp = gru_wih + (size_t)k0 * H3 + j;
        float a0 = 0.f, a1 = 0.f, a2 = 0.f, a3 = 0.f;
#pragma unroll 8
        for (int k = 0; k < 32; ++k) {
            float xv = fmaxf(s[XPRE_OFF + k0 + k], 0.f);
            float4 w = *(const float4*)Wp;
            a0 = fmaf(xv, w.x, a0); a1 = fmaf(xv, w.y, a1);
            a2 = fmaf(xv, w.z, a2); a3 = fmaf(xv, w.w, a3);
            Wp += H3;
        }
        atomicAdd(&s[GI_OFF + j],     a0); atomicAdd(&s[GI_OFF + j + 1], a1);
        atomicAdd(&s[GI_OFF + j + 2], a2); atomicAdd(&s[GI_OFF + j + 3], a3);
    }
    grid_bar(5, NBLK);

    // ---- P6: GRU gates -> h_new (blocks 0..3) ----
    if (bid < 4) {
        int i = bid * 256 + t;   // 0..1023
        const float* gi = s + GI_OFF;
        const float* gh = s + GH_OFF;
        float r = 1.f / (1.f + expf(-(gi[i] + gh[i])));
        float z = 1.f / (1.f + expf(-(gi[H + i] + gh[H + i])));
        float n = tanhf(gi[2 * H + i] + r * gh[2 * H + i]);
        float hn = (1.f - z) * n + z * hidden[i];
        s[HNEW_OFF + i] = hn;
        hnew_out[i] = hn;
    }
}

// ---------------------------------------------------------------------------
// Logits + fused log-softmax: 786 blocks x 64 threads (all co-resident:
// needs ~5.3 blocks/SM, cap is 32/SM at 4.2KB smem + 64 threads).
// Each thread computes one logit, contributes exp to gsum, grid-barriers,
// then writes the FINAL logprob once.
// ---------------------------------------------------------------------------
__global__ void __launch_bounds__(64, 32)
logits_kernel(const float* __restrict__ hnew,
              const float* __restrict__ W,
              const float* __restrict__ bias,
              float* __restrict__ logits,
              float* __restrict__ gsum) {
    __shared__ float hs[H];
    __shared__ float lse_s;
    int t = threadIdx.x;  // 64
    for (int i = t; i < H; i += 64) hs[i] = hnew[i];
    __syncthreads();
    int j = blockIdx.x * 64 + t;
    bool valid = (j < V);
    float acc = 0.f;
    if (valid) {
        acc = bias[j];
        const float* Wp = W + j;
#pragma unroll 32
        for (int k = 0; k < H; ++k)
            acc = fmaf(hs[k], Wp[(size_t)k * V], acc);
    }
    float ex = valid ? expf(acc) : 0.f;
#pragma unroll
    for (int o = 16; o; o >>= 1) ex += __shfl_xor_sync(0xffffffffu, ex, o);
    if ((t & 31) == 0) atomicAdd(gsum, ex);

    // grid barrier (index 6) with gsum pickup between spin and depart
    __threadfence();
    __syncthreads();
    if (t == 0) {
        unsigned n = gridDim.x;
        atomicAdd(&g_arrive[6], 1u);
        while (*(volatile unsigned*)&g_arrive[6] < n) __nanosleep(64);
        lse_s = logf(*(volatile float*)gsum);
        unsigned d = atomicAdd(&g_depart[6], 1u);
        if (d == n - 1u) {
            *(volatile unsigned*)&g_depart[6] = 0u;
            __threadfence();
            *(volatile unsigned*)&g_arrive[6] = 0u;
        }
    }
    __syncthreads();
    if (valid) logits[j] = acc - lse_s;
}

// ---------------------------------------------------------------------------
extern "C" void kernel_launch(void* const* d_in, const int* in_sizes, int n_in,
                              void* d_out, int out_size) {
    const int*   idx      = (const int*)d_in[0];   // int64 LE: low word = value
    const float* hidden   = (const float*)d_in[1];
    const float* enc      = (const float*)d_in[2];
    const float* emb      = (const float*)d_in[3];
    const float* attn_w_W = (const float*)d_in[4];
    const float* attn_w_b = (const float*)d_in[5];
    const float* attn_v_W = (const float*)d_in[6];
    const float* attn_v_b = (const float*)d_in[7];
    const float* comb_W   = (const float*)d_in[8];
    const float* comb_b   = (const float*)d_in[9];
    const float* gru_wih  = (const float*)d_in[10];
    const float* gru_bih  = (const float*)d_in[11];
    const float* gru_whh  = (const float*)d_in[12];
    const float* gru_bhh  = (const float*)d_in[13];
    const float* out_W    = (const float*)d_in[14];
    const float* out_b    = (const float*)d_in[15];
    float* out = (float*)d_out;   // [V logprobs][H h_new][L attn_weights]

    float* s = nullptr;
    cudaGetSymbolAddress((void**)&s, g_scratch);

    fused_chain_kernel<<<148, 256>>>(hidden, enc, emb, idx,
                                     attn_w_W, attn_w_b, attn_v_W, attn_v_b,
                                     comb_W, comb_b, gru_wih, gru_bih,
                                     gru_whh, gru_bhh,
                                     s, out + V, out + V + H);

    logits_kernel<<<(V + 63) / 64, 64>>>(s + HNEW_OFF, out_W, out_b, out,
                                         s + SUM_OFF);
}

// round 9
// speedup vs baseline: 2.5851x; 1.2842x over previous
#include <cuda_runtime.h>
#include <cuda_bf16.h>
#include <math.h>

// Problem dims
#define H   1024
#define H3  3072
#define V   50257
#define L   50
#define ENC 2048

// Scratch layout (floats)
#define A_OFF      0          // 1024 : h@W_h + attn_w_b
#define GH_OFF     1024       // 3072 : h@gru_whh + gru_bhh
#define B_OFF      4096       // 50*1024 : enc@W_e
#define XIN_OFF    55296      // 3072 : [emb_row, attn_applied]
#define XPRE_OFF   58368      // 1024 : xin@comb_W + comb_b (pre-relu)
#define GI_OFF     59392      // 3072 : relu(xpre)@gru_wih + gru_bih
#define HNEW_OFF   62464      // 1024
#define SE_OFF     63600      // 50 : attention scores
#define SUM_OFF    63520      // 1  : global sum(exp(logit))
#define SCRATCH_ELEMS 65536

__device__ float g_scratch[SCRATCH_ELEMS];

// Self-resetting grid barriers (arrive/depart pairs). Zero at module load;
// last departer resets both counters -> replay-safe.
__device__ unsigned g_arrive[8];
__device__ unsigned g_depart[8];

__device__ __forceinline__ void grid_bar(int i, unsigned n) {
    __threadfence();
    __syncthreads();
    if (threadIdx.x == 0) {
        atomicAdd(&g_arrive[i], 1u);
        while (*(volatile unsigned*)&g_arrive[i] < n) __nanosleep(64);
        unsigned d = atomicAdd(&g_depart[i], 1u);
        if (d == n - 1u) {
            *(volatile unsigned*)&g_depart[i] = 0u;
            __threadfence();
            *(volatile unsigned*)&g_arrive[i] = 0u;
        }
    }
    __syncthreads();
    __threadfence();
}

// ---------------------------------------------------------------------------
// Fused small-op chain: 296 blocks x 256 threads (2/SM, exact co-residency).
// P0 init (+ logits=bias) -> P1 {h-GEMVs + enc GEMM} -> P2 scores ->
// P3 softmax/apply/xin -> P4 comb -> P5 gih -> P6 GRU gates.
// ---------------------------------------------------------------------------
#define LB 10
__global__ void __launch_bounds__(256, 2)
fused_chain_kernel(const float* __restrict__ hidden,
                   const float* __restrict__ enc,
                   const float* __restrict__ emb,
                   const int*   __restrict__ idx,
                   const float* __restrict__ attn_w_W,
                   const float* __restrict__ attn_w_b,
                   const float* __restrict__ attn_v_W,
                   const float* __restrict__ attn_v_b,
                   const float* __restrict__ comb_W,
                   const float* __restrict__ comb_b,
                   const float* __restrict__ gru_wih,
                   const float* __restrict__ gru_bih,
                   const float* __restrict__ gru_whh,
                   const float* __restrict__ gru_bhh,
                   const float* __restrict__ out_b,
                   float* __restrict__ s,
                   float* __restrict__ logits,
                   float* __restrict__ hnew_out,
                   float* __restrict__ attw_out) {
    __shared__ float sm[704];      // enc tile (640) / softmax se+sw (100)
    __shared__ float ws[8];
    const unsigned NBLK = gridDim.x;     // 296
    const int bid = blockIdx.x;
    const int t = threadIdx.x;
    const int lane = t & 31, warp = t >> 5;

    // ---- P0: biases into accumulators, zero B, logits=bias, reset gsum ----
    {
        int gid = bid * 256 + t, stride = NBLK * 256;
        for (int i = gid; i < L * H; i += stride) s[B_OFF + i] = 0.f;
        for (int i = gid; i < H;    i += stride) s[A_OFF + i] = attn_w_b[i];
        for (int i = gid; i < H3;   i += stride) s[GH_OFF + i] = gru_bhh[i];
        for (int i = gid; i < H3;   i += stride) s[GI_OFF + i] = gru_bih[i];
        for (int i = gid; i < H;    i += stride) s[XPRE_OFF + i] = comb_b[i];
        for (int i = gid; i < V;    i += stride) logits[i] = out_b[i];
        for (int i = gid; i < L;    i += stride) s[SE_OFF + i] = attn_v_b[0];
        if (gid == 0) s[SUM_OFF] = 0.f;
    }
    grid_bar(0, NBLK);

    // ---- P1: units 0..127 dual h-GEMV; units 128..767 enc GEMM ----
    for (int u = bid; u < 768; u += NBLK) {
        if (u < 128) {
            int ju = u & 3, ku = u >> 2;           // 32 k-splits of 32
            const float* W; float* out; int N, jb;
            if (ju == 0) { W = attn_w_W; out = s + A_OFF;  N = 1024; jb = 0; }
            else         { W = gru_whh;  out = s + GH_OFF; N = 3072; jb = (ju - 1) * 1024; }
            int j = jb + t * 4;
            int k0 = ku * 32;
            const float* Wp = W + (size_t)k0 * N + j;
            float a0 = 0.f, a1 = 0.f, a2 = 0.f, a3 = 0.f;
#pragma unroll 8
            for (int k = 0; k < 32; ++k) {
                float xv = __ldg(&hidden[k0 + k]);
                float4 w = *(const float4*)Wp;
                a0 = fmaf(xv, w.x, a0); a1 = fmaf(xv, w.y, a1);
                a2 = fmaf(xv, w.z, a2); a3 = fmaf(xv, w.w, a3);
                Wp += N;
            }
            atomicAdd(&out[j],     a0); atomicAdd(&out[j + 1], a1);
            atomicAdd(&out[j + 2], a2); atomicAdd(&out[j + 3], a3);
        } else {
            int e = u - 128;                        // 640 units: 4j x 32k x 5l
            int uj = e & 3, uk = (e >> 2) & 31, ul = e >> 7;
            int j = uj * 256 + t, k0 = uk * 64, l0 = ul * LB;
            __syncthreads();
            for (int i = t; i < LB * 64; i += 256) {
                int l = i >> 6, kk = i & 63;
                sm[i] = enc[(l0 + l) * ENC + k0 + kk];
            }
            __syncthreads();
            float acc[LB];
#pragma unroll
            for (int l = 0; l < LB; ++l) acc[l] = 0.f;
            const float* Wp = attn_w_W + (size_t)H * H + (size_t)k0 * H + j;
#pragma unroll 8
            for (int kk = 0; kk < 64; ++kk) {
                float w = Wp[(size_t)kk * H];
#pragma unroll
                for (int l = 0; l < LB; ++l)
                    acc[l] = fmaf(w, sm[l * 64 + kk], acc[l]);
            }
#pragma unroll
            for (int l = 0; l < LB; ++l)
                atomicAdd(&s[B_OFF + (l0 + l) * H + j], acc[l]);
        }
    }
    grid_bar(1, NBLK);

    // ---- P2: scores se[l] += relu(a + B[l]) @ v  (100 half-units) ----
    if (bid < 100) {
        int l = bid >> 1, half = bid & 1;
        const float* a  = s + A_OFF + half * 512;
        const float* Bl = s + B_OFF + l * H + half * 512;
        const float* vv = attn_v_W + half * 512;
        float p = 0.f;
#pragma unroll
        for (int jj = t; jj < 512; jj += 256)
            p = fmaf(fmaxf(a[jj] + Bl[jj], 0.f), vv[jj], p);
#pragma unroll
        for (int o = 16; o; o >>= 1) p += __shfl_xor_sync(0xffffffffu, p, o);
        if (lane == 0) ws[warp] = p;
        __syncthreads();
        if (t == 0) {
            float acc = ws[0];
#pragma unroll
            for (int w = 1; w < 8; ++w) acc += ws[w];
            atomicAdd(&s[SE_OFF + l], acc);
        }
    }
    grid_bar(2, NBLK);

    // ---- P3: softmax + attn_applied + xin assembly (blocks 0..8) ----
    if (bid <= 8) {
        float* se = sm;        // [50]
        float* sw = sm + 64;   // [50]
        __syncthreads();
        if (t < L) se[t] = s[SE_OFF + t];
        __syncthreads();
        if (t < L) {
            float m = -3.0e38f;
#pragma unroll
            for (int l = 0; l < L; ++l) m = fmaxf(m, se[l]);
            float sum = 0.f;
#pragma unroll
            for (int l = 0; l < L; ++l) sum += expf(se[l] - m);
            sw[t] = expf(se[t] - m) / sum;
        }
        __syncthreads();
        float* xin = s + XIN_OFF;
        if (bid < 8) {
            int col = bid * 256 + t;               // 0..2047
            float acc = 0.f;
#pragma unroll 10
            for (int l = 0; l < L; ++l)
                acc = fmaf(sw[l], enc[l * ENC + col], acc);
            xin[H + col] = acc;
        } else {
            if (t < L) attw_out[t] = sw[t];
            int id = idx[0];
            for (int i = t; i < H; i += 256)
                xin[i] = emb[(size_t)id * H + i];
        }
    }
    grid_bar(3, NBLK);

    // ---- P4: xpre += xin @ comb_W   (64 k-splits of 48) ----
    if (bid < 64) {
        int j = t * 4;
        int k0 = bid * 48;
        const float* Wp = comb_W + (size_t)k0 * H + j;
        float a0 = 0.f, a1 = 0.f, a2 = 0.f, a3 = 0.f;
#pragma unroll 8
        for (int k = 0; k < 48; ++k) {
            float xv = s[XIN_OFF + k0 + k];
            float4 w = *(const float4*)Wp;
            a0 = fmaf(xv, w.x, a0); a1 = fmaf(xv, w.y, a1);
            a2 = fmaf(xv, w.z, a2); a3 = fmaf(xv, w.w, a3);
            Wp += H;
        }
        atomicAdd(&s[XPRE_OFF + j],     a0); atomicAdd(&s[XPRE_OFF + j + 1], a1);
        atomicAdd(&s[XPRE_OFF + j + 2], a2); atomicAdd(&s[XPRE_OFF + j + 3], a3);
    }
    grid_bar(4, NBLK);

    // ---- P5: gi += relu(xpre) @ gru_wih  (3 j-tiles x 32 k-splits) ----
    if (bid < 96) {
        int ju = bid % 3, ku = bid / 3;
        int j = ju * 1024 + t * 4;
        int k0 = ku * 32;
        const float* Wp = gru_wih + (size_t)k0 * H3 + j;
        float a0 = 0.f, a1 = 0.f, a2 = 0.f, a3 = 0.f;
#pragma unroll 8
        for (int k = 0; k < 32; ++k) {
            float xv = fmaxf(s[XPRE_OFF + k0 + k], 0.f);
            float4 w = *(const float4*)Wp;
            a0 = fmaf(xv, w.x, a0); a1 = fmaf(xv, w.y, a1);
            a2 = fmaf(xv, w.z, a2); a3 = fmaf(xv, w.w, a3);
            Wp += H3;
        }
        atomicAdd(&s[GI_OFF + j],     a0); atomicAdd(&s[GI_OFF + j + 1], a1);
        atomicAdd(&s[GI_OFF + j + 2], a2); atomicAdd(&s[GI_OFF + j + 3], a3);
    }
    grid_bar(5, NBLK);

    // ---- P6: GRU gates -> h_new (blocks 0..3) ----
    if (bid < 4) {
        int i = bid * 256 + t;   // 0..1023
        const float* gi = s + GI_OFF;
        const float* gh = s + GH_OFF;
        float r = 1.f / (1.f + expf(-(gi[i] + gh[i])));
        float z = 1.f / (1.f + expf(-(gi[H + i] + gh[H + i])));
        float n = tanhf(gi[2 * H + i] + r * gh[2 * H + i]);
        float hn = (1.f - z) * n + z * hidden[i];
        s[HNEW_OFF + i] = hn;
        hnew_out[i] = hn;
    }
}

// ---------------------------------------------------------------------------
// Vocab GEMV, split-K x4 + fused log-softmax.
// 788 blocks x 256 threads: 197 j-tiles x 4 k-splits of 256.
// logits pre-initialized with bias by the chain kernel.
// __launch_bounds__(256,6): regs<=42 -> 888 resident slots >= 788 (barrier-safe).
// ---------------------------------------------------------------------------
#define JT 197
__global__ void __launch_bounds__(256, 6)
logits_kernel(const float* __restrict__ hnew,
              const float* __restrict__ W,
              float* __restrict__ logits,
              float* __restrict__ gsum) {
    __shared__ float hs[256];
    __shared__ float lse_s;
    const unsigned NBLK = gridDim.x;   // 788
    int t = threadIdx.x;
    int tile = blockIdx.x % JT;
    int ks = blockIdx.x / JT;          // 0..3
    int k0 = ks * 256;

    hs[t] = hnew[k0 + t];
    __syncthreads();

    int j = tile * 256 + t;
    if (j < V) {
        float acc = 0.f;
        const float* Wp = W + (size_t)k0 * V + j;
#pragma unroll 8
        for (int k = 0; k < 256; ++k) {
            acc = fmaf(hs[k], *Wp, acc);
            Wp += V;
        }
        atomicAdd(&logits[j], acc);
    }
    grid_bar(6, NBLK);

    // exp-sum over final logits (gsum zeroed by chain P0)
    {
        int gid = blockIdx.x * 256 + t, stride = NBLK * 256;
        float ex = 0.f;
        for (int jj = gid; jj < V; jj += stride) ex += expf(logits[jj]);
#pragma unroll
        for (int o = 16; o; o >>= 1) ex += __shfl_xor_sync(0xffffffffu, ex, o);
        if ((t & 31) == 0 && ex != 0.f) atomicAdd(gsum, ex);
    }

    // barrier 7 with lse pickup between spin and depart
    __threadfence();
    __syncthreads();
    if (t == 0) {
        atomicAdd(&g_arrive[7], 1u);
        while (*(volatile unsigned*)&g_arrive[7] < NBLK) __nanosleep(64);
        lse_s = logf(*(volatile float*)gsum);
        unsigned d = atomicAdd(&g_depart[7], 1u);
        if (d == NBLK - 1u) {
            *(volatile unsigned*)&g_depart[7] = 0u;
            __threadfence();
            *(volatile unsigned*)&g_arrive[7] = 0u;
        }
    }
    __syncthreads();

    {
        int gid = blockIdx.x * 256 + t, stride = NBLK * 256;
        float lse = lse_s;
        for (int jj = gid; jj < V; jj += stride) logits[jj] -= lse;
    }
}

// ---------------------------------------------------------------------------
extern "C" void kernel_launch(void* const* d_in, const int* in_sizes, int n_in,
                              void* d_out, int out_size) {
    const int*   idx      = (const int*)d_in[0];   // int64 LE: low word = value
    const float* hidden   = (const float*)d_in[1];
    const float* enc      = (const float*)d_in[2];
    const float* emb      = (const float*)d_in[3];
    const float* attn_w_W = (const float*)d_in[4];
    const float* attn_w_b = (const float*)d_in[5];
    const float* attn_v_W = (const float*)d_in[6];
    const float* attn_v_b = (const float*)d_in[7];
    const float* comb_W   = (const float*)d_in[8];
    const float* comb_b   = (const float*)d_in[9];
    const float* gru_wih  = (const float*)d_in[10];
    const float* gru_bih  = (const float*)d_in[11];
    const float* gru_whh  = (const float*)d_in[12];
    const float* gru_bhh  = (const float*)d_in[13];
    const float* out_W    = (const float*)d_in[14];
    const float* out_b    = (const float*)d_in[15];
    float* out = (float*)d_out;   // [V logprobs][H h_new][L attn_weights]

    float* s = nullptr;
    cudaGetSymbolAddress((void**)&s, g_scratch);

    fused_chain_kernel<<<296, 256>>>(hidden, enc, emb, idx,
                                     attn_w_W, attn_w_b, attn_v_W, attn_v_b,
                                     comb_W, comb_b, gru_wih, gru_bih,
                                     gru_whh, gru_bhh, out_b,
                                     s, out, out + V, out + V + H);

    logits_kernel<<<JT * 4, 256>>>(s + HNEW_OFF, out_W, out, s + SUM_OFF);
}